// round 7
// baseline (speedup 1.0000x reference)
#include <cuda_runtime.h>
#include <cuda_bf16.h>

#define NATOMS 6144
#define F 128
#define G 48
#define MT 32                  // GEMM M tile
#define KC 16                  // GEMM K chunk
#define MTILES (NATOMS / MT)   // 192
#define KE_CONST 14.3996f

typedef unsigned long long u64;

// ---------------- scratch ----------------
__device__ float    g_q[NATOMS];
__device__ float    g_qc[NATOMS];   // centered q
__device__ float    g_sc6[NATOMS];
__device__ float    g_r3[NATOMS];
__device__ int      g_start[G];
__device__ int      g_cnt[G];
__device__ double   g_esum;
__device__ unsigned g_done;

__device__ __forceinline__ float softplusf(float x) {
    return fmaxf(x, 0.0f) + log1pf(expf(-fabsf(x)));
}
__device__ __forceinline__ float siluf(float x) {
    return x / (1.0f + expf(-x));
}

// packed fp32x2 FMA (sm_100+)
#define FMA2(acc, w, x) asm("fma.rn.f32x2 %0, %1, %2, %0;" : "+l"(acc) : "l"(w), "l"(x))

__device__ __forceinline__ void unpack2(u64 p, float &lo, float &hi) {
    asm("mov.b64 {%0,%1}, %2;" : "=f"(lo), "=f"(hi) : "l"(p));
}
__device__ __forceinline__ unsigned smem_u32(const void* p) {
    return (unsigned)__cvta_generic_to_shared(p);
}
__device__ __forceinline__ void cp16(unsigned dst, const void* src) {
    asm volatile("cp.async.ca.shared.global [%0], [%1], 16;\n" :: "r"(dst), "l"(src));
}
#define CP_COMMIT() asm volatile("cp.async.commit_group;\n" ::: "memory")
#define CP_WAIT0()  asm volatile("cp.async.wait_group 0;\n" ::: "memory")

// ================= K1: fused MLP GEMM (256 threads, double-buffered) ======
// grid = 2*MTILES + 1.  bid < 2*MTILES: GEMM block (head = bid/MTILES,
// m-tile = bid%MTILES).  Last block: segment bounds + accumulator reset.
// 256 threads: ng = tid&15 (8 n-cols), mg = tid>>4 (2 m-rows).
__global__ __launch_bounds__(256) void mlp_gemm_kernel(
    const float* __restrict__ h0,
    const float* __restrict__ qW1, const float* __restrict__ qb1,
    const float* __restrict__ qW2,
    const float* __restrict__ vW1, const float* __restrict__ vb1,
    const float* __restrict__ vW2, const float* __restrict__ vb2,
    const int*   __restrict__ batch)
{
    const int bid = blockIdx.x;
    const int tid = threadIdx.x;

    if (bid == 2 * MTILES) {
        if (tid == 0) { g_esum = 0.0; g_done = 0u; }
        __shared__ int ss[G + 1];
        if (tid <= G) {
            int lo = 0, hi = NATOMS;
            while (lo < hi) {
                int m = (lo + hi) >> 1;
                if (batch[m] < tid) lo = m + 1; else hi = m;
            }
            ss[tid] = lo;
        }
        __syncthreads();
        if (tid < G) { g_start[tid] = ss[tid]; g_cnt[tid] = ss[tid + 1] - ss[tid]; }
        return;
    }

    const int head  = bid / MTILES;          // 0 = charge, 1 = vdw
    const int mbase = (bid % MTILES) * MT;
    const int ng = tid & 15;
    const int mg = tid >> 4;                 // 0..15

    const float* __restrict__ W1 = head ? vW1 : qW1;
    const float* __restrict__ B1 = head ? vb1 : qb1;

    // A broadcast-packed: As[buf][k][m] float2, stride 34 (272B = 17x16B)
    __shared__ float2 As[2][KC][34];
    __shared__ float  Bs[2][KC][F];

    u64 acc[2][4];
#pragma unroll
    for (int i = 0; i < 2; i++)
#pragma unroll
        for (int j = 0; j < 4; j++) acc[i][j] = 0ull;

    const int am = tid >> 3;           // A: m row 0..31
    const int ak = (tid & 7) * 2;      // A: 2 k values

    // prologue: chunk 0
    float2 av = *(const float2*)&h0[(mbase + am) * F + ak];
#pragma unroll
    for (int i = 0; i < 2; i++)
        cp16(smem_u32(&Bs[0][0][0]) + (i * 256 + tid) * 16,
             (const char*)(W1) + (i * 256 + tid) * 16);
    CP_COMMIT();

    for (int c = 0; c < F / KC; c++) {
        const int buf = c & 1;
        As[buf][ak + 0][am] = make_float2(av.x, av.x);
        As[buf][ak + 1][am] = make_float2(av.y, av.y);
        CP_WAIT0();
        __syncthreads();
        if (c < F / KC - 1) {
            av = *(const float2*)&h0[(mbase + am) * F + (c + 1) * KC + ak];
            const char* src = (const char*)(W1 + (c + 1) * KC * F);
            unsigned dst = smem_u32(&Bs[buf ^ 1][0][0]);
#pragma unroll
            for (int i = 0; i < 2; i++)
                cp16(dst + (i * 256 + tid) * 16, src + (i * 256 + tid) * 16);
            CP_COMMIT();
        }

#pragma unroll
        for (int r = 0; r < KC; r++) {
            ulonglong2 a01 = *(const ulonglong2*)&As[buf][r][mg * 2];
            ulonglong2 b01 = *(const ulonglong2*)&Bs[buf][r][ng * 8 + 0];
            ulonglong2 b23 = *(const ulonglong2*)&Bs[buf][r][ng * 8 + 4];
            FMA2(acc[0][0], b01.x, a01.x); FMA2(acc[0][1], b01.y, a01.x);
            FMA2(acc[0][2], b23.x, a01.x); FMA2(acc[0][3], b23.y, a01.x);
            FMA2(acc[1][0], b01.x, a01.y); FMA2(acc[1][1], b01.y, a01.y);
            FMA2(acc[1][2], b23.x, a01.y); FMA2(acc[1][3], b23.y, a01.y);
        }
        __syncthreads();
    }

    // ---- fused second layer: silu + dot(w2) + reduce over ng ----
    const int n0 = ng * 8;
    float b1v[8], w2a[8], w2b[8];
#pragma unroll
    for (int j = 0; j < 8; j++) {
        b1v[j] = B1[n0 + j];
        if (head) { w2a[j] = vW2[2 * (n0 + j)]; w2b[j] = vW2[2 * (n0 + j) + 1]; }
        else      { w2a[j] = qW2[n0 + j];       w2b[j] = 0.0f; }
    }

#pragma unroll
    for (int i = 0; i < 2; i++) {
        float s0 = 0.f, s1 = 0.f;
#pragma unroll
        for (int j = 0; j < 4; j++) {
            float c0, c1; unpack2(acc[i][j], c0, c1);
            float h0v = siluf(c0 + b1v[2 * j]);
            float h1v = siluf(c1 + b1v[2 * j + 1]);
            s0 += h0v * w2a[2 * j] + h1v * w2a[2 * j + 1];
            s1 += h0v * w2b[2 * j] + h1v * w2b[2 * j + 1];
        }
#pragma unroll
        for (int m = 8; m >= 1; m >>= 1) {
            s0 += __shfl_xor_sync(0xFFFFFFFFu, s0, m);
            s1 += __shfl_xor_sync(0xFFFFFFFFu, s1, m);
        }
        if (ng == 0) {
            int atom = mbase + mg * 2 + i;
            if (head == 0) {
                g_q[atom] = s0;
            } else {
                float c6 = softplusf(s0 + vb2[0]);
                float rv = softplusf(s1 + vb2[1]);
                g_sc6[atom] = sqrtf(c6);
                g_r3[atom]  = rv * rv * rv;
            }
        }
    }
}

// ================= K2: per-graph q centering =================
__global__ __launch_bounds__(128) void qcenter_kernel() {
    __shared__ float wred[4];
    const int g = blockIdx.x;
    const int s = g_start[g];
    const int c = g_cnt[g];
    const int tid = threadIdx.x;
    const int lane = tid & 31, wrp = tid >> 5;

    float acc = 0.f;
    for (int t = tid; t < c; t += 128) acc += g_q[s + t];
#pragma unroll
    for (int o = 16; o > 0; o >>= 1) acc += __shfl_xor_sync(0xFFFFFFFFu, acc, o);
    if (lane == 0) wred[wrp] = acc;
    __syncthreads();
    float mean = (wred[0] + wred[1] + wred[2] + wred[3]) / fmaxf((float)c, 1.0f);
    for (int t = tid; t < c; t += 128) g_qc[s + t] = g_q[s + t] - mean;
}

// ================= K3: pairwise (flat warp-per-row) + reduction ==========
__global__ __launch_bounds__(256) void pair_kernel(
    const float* __restrict__ pos,
    const int*   __restrict__ batch,
    const float* __restrict__ sigma,
    float* __restrict__ out)
{
    __shared__ float wred[8];
    const int tid  = threadIdx.x;
    const int lane = tid & 31;
    const int wrp  = tid >> 5;
    const int nw   = gridDim.x * 8;
    int w = blockIdx.x * 8 + wrp;

    const float invs = 1.0f / (1.41421356f * sigma[0]);

    float eel = 0.f, evd = 0.f;
    for (int i = w; i < NATOMS; i += nw) {
        const int g = batch[i];
        const int e = g_start[g] + g_cnt[g];
        const float px = pos[3 * i + 0];
        const float py = pos[3 * i + 1];
        const float pz = pos[3 * i + 2];
        const float qi = g_qc[i];
        const float c6i = g_sc6[i];
        const float r3i = g_r3[i];
        for (int j = i + 1 + lane; j < e; j += 32) {
            float dx = px - pos[3 * j + 0];
            float dy = py - pos[3 * j + 1];
            float dz = pz - pos[3 * j + 2];
            float dsq = dx * dx + dy * dy + dz * dz;
            float dist = sqrtf(dsq + 1e-8f);
            eel += qi * g_qc[j] * __fdividef(erff(dist * invs), dist + 1e-8f);
            float damp = dsq * dsq * dsq + r3i * g_r3[j];
            evd -= __fdividef(c6i * g_sc6[j], damp + 1e-8f);
        }
    }

    float tot = KE_CONST * eel + evd;   // unordered pairs: 2 * 0.5 = 1
#pragma unroll
    for (int o = 16; o > 0; o >>= 1) tot += __shfl_down_sync(0xFFFFFFFFu, tot, o);
    if (lane == 0) wred[wrp] = tot;
    __syncthreads();
    if (tid == 0) {
        float bs = 0.f;
        for (int i = 0; i < 8; i++) bs += wred[i];
        atomicAdd(&g_esum, (double)bs);
        __threadfence();
        unsigned t = atomicAdd(&g_done, 1u);
        if (t == gridDim.x - 1) {
            g_done = 0u;
            double total = atomicAdd(&g_esum, 0.0);
            out[0] = (float)total;
        }
    }
}

// ---------------- launch ----------------
extern "C" void kernel_launch(void* const* d_in, const int* in_sizes, int n_in,
                              void* d_out, int out_size) {
    const float* h0    = (const float*)d_in[0];
    const float* pos   = (const float*)d_in[2];
    const float* qW1   = (const float*)d_in[3];
    const float* qb1   = (const float*)d_in[4];
    const float* qW2   = (const float*)d_in[5];
    const float* sigma = (const float*)d_in[6];
    const float* vW1   = (const float*)d_in[7];
    const float* vb1   = (const float*)d_in[8];
    const float* vW2   = (const float*)d_in[9];
    const float* vb2   = (const float*)d_in[10];
    const int*   batch = (const int*)d_in[11];

    mlp_gemm_kernel<<<2 * MTILES + 1, 256>>>(h0, qW1, qb1, qW2,
                                             vW1, vb1, vW2, vb2, batch);
    qcenter_kernel<<<G, 128>>>();
    pair_kernel<<<296, 256>>>(pos, batch, sigma, (float*)d_out);
}

// round 9
// speedup vs baseline: 1.6429x; 1.6429x over previous
#include <cuda_runtime.h>
#include <cuda_bf16.h>

#define NATOMS 6144
#define F 128
#define G 48
#define MT 32                  // GEMM M tile
#define KC 16                  // GEMM K chunk (B staging)
#define MTILES (NATOMS / MT)   // 192
#define SPLIT 12               // pair blocks per graph
#define MAXC 256
#define KE_CONST 14.3996f

typedef unsigned long long u64;

// ---------------- scratch ----------------
__device__ float    g_q[NATOMS];
__device__ float    g_sc6[NATOMS];
__device__ float    g_r3[NATOMS];
__device__ int      g_start[G];
__device__ int      g_cnt[G];
__device__ double   g_esum;
__device__ unsigned g_done;

__device__ __forceinline__ float softplusf(float x) {
    return fmaxf(x, 0.0f) + log1pf(expf(-fabsf(x)));
}
__device__ __forceinline__ float siluf(float x) {
    return x / (1.0f + expf(-x));
}

// packed fp32x2 FMA (sm_100+)
#define FMA2(acc, w, x) asm("fma.rn.f32x2 %0, %1, %2, %0;" : "+l"(acc) : "l"(w), "l"(x))

__device__ __forceinline__ u64 dup2(float x) {
    u64 r; asm("mov.b64 %0, {%1,%1};" : "=l"(r) : "f"(x)); return r;
}
__device__ __forceinline__ void unpack2(u64 p, float &lo, float &hi) {
    asm("mov.b64 {%0,%1}, %2;" : "=f"(lo), "=f"(hi) : "l"(p));
}
__device__ __forceinline__ unsigned smem_u32(const void* p) {
    return (unsigned)__cvta_generic_to_shared(p);
}
__device__ __forceinline__ void cp16(unsigned dst, const void* src) {
    asm volatile("cp.async.ca.shared.global [%0], [%1], 16;\n" :: "r"(dst), "l"(src));
}
#define CP_COMMIT() asm volatile("cp.async.commit_group;\n" ::: "memory")
#define CP_WAIT0()  asm volatile("cp.async.wait_group 0;\n" ::: "memory")

// ================= K1: fused MLP GEMM =================
// grid = 2*MTILES + 1 = 385 blocks of 64 threads.
// bid < 2*MTILES: GEMM block (head = bid/MTILES, m-tile = bid%MTILES).
// Last block: segment bounds + accumulator reset.
// Thread layout: ng = tid&15 (8 n-cols each -> N=128), mg = tid>>4 (8 atoms -> M=32).
// Per-thread register tile: 4 m-pairs x 8 n  (u64 accumulators, f32x2 math).
__global__ __launch_bounds__(64) void mlp_gemm_kernel(
    const float* __restrict__ h0,
    const float* __restrict__ qW1, const float* __restrict__ qb1,
    const float* __restrict__ qW2,
    const float* __restrict__ vW1, const float* __restrict__ vb1,
    const float* __restrict__ vW2, const float* __restrict__ vb2,
    const int*   __restrict__ batch)
{
    const int bid = blockIdx.x;
    const int tid = threadIdx.x;

    if (bid == 2 * MTILES) {
        if (tid == 0) { g_esum = 0.0; g_done = 0u; }
        __shared__ int ss[G + 1];
        if (tid <= G) {
            int lo = 0, hi = NATOMS;
            while (lo < hi) {
                int m = (lo + hi) >> 1;
                if (batch[m] < tid) lo = m + 1; else hi = m;
            }
            ss[tid] = lo;
        }
        __syncthreads();
        if (tid < G) { g_start[tid] = ss[tid]; g_cnt[tid] = ss[tid + 1] - ss[tid]; }
        return;
    }

    const int head  = bid / MTILES;          // 0 = charge, 1 = vdw
    const int mbase = (bid % MTILES) * MT;
    const int ng = tid & 15;
    const int mg = tid >> 4;                 // 0..3

    const float* __restrict__ W1 = head ? vW1 : qW1;
    const float* __restrict__ B1 = head ? vb1 : qb1;

    // A: full tile [k][m], k-major rows of 32 atoms, pad to 34 (136B, 8B-aligned)
    __shared__ float As[F][34];
    __shared__ float Bs[2][KC][F];

    // ---- prologue: B chunk 0 via cp.async ----
    {
        unsigned dst = smem_u32(&Bs[0][0][0]);
        const char* src = (const char*)W1;
#pragma unroll
        for (int i = 0; i < 8; i++)
            cp16(dst + (i * 64 + tid) * 16, src + (i * 64 + tid) * 16);
        CP_COMMIT();
    }

    // ---- fill A tile (transpose to [k][m]) ----
    {
        const int atom  = tid >> 1;          // 0..31
        const int khalf = (tid & 1) * 64;    // 0 or 64
        const float4* src = (const float4*)&h0[(mbase + atom) * F + khalf];
#pragma unroll
        for (int kk = 0; kk < 16; kk++) {
            float4 v = src[kk];
            int k = khalf + kk * 4;
            As[k + 0][atom] = v.x;
            As[k + 1][atom] = v.y;
            As[k + 2][atom] = v.z;
            As[k + 3][atom] = v.w;
        }
    }

    u64 acc[4][8];
#pragma unroll
    for (int p = 0; p < 4; p++)
#pragma unroll
        for (int j = 0; j < 8; j++) acc[p][j] = 0ull;

    for (int c = 0; c < F / KC; c++) {
        const int buf = c & 1;
        CP_WAIT0();
        __syncthreads();
        if (c < F / KC - 1) {
            unsigned dst = smem_u32(&Bs[buf ^ 1][0][0]);
            const char* src = (const char*)(W1 + (c + 1) * KC * F);
#pragma unroll
            for (int i = 0; i < 8; i++)
                cp16(dst + (i * 64 + tid) * 16, src + (i * 64 + tid) * 16);
            CP_COMMIT();
        }

#pragma unroll
        for (int r = 0; r < KC; r++) {
            const int k = c * KC + r;
            const u64* ap = (const u64*)&As[k][mg * 8];
            u64 a0 = ap[0], a1 = ap[1], a2 = ap[2], a3 = ap[3];
            float4 b03 = *(const float4*)&Bs[buf][r][ng * 8 + 0];
            float4 b47 = *(const float4*)&Bs[buf][r][ng * 8 + 4];
            u64 bb0 = dup2(b03.x), bb1 = dup2(b03.y);
            u64 bb2 = dup2(b03.z), bb3 = dup2(b03.w);
            u64 bb4 = dup2(b47.x), bb5 = dup2(b47.y);
            u64 bb6 = dup2(b47.z), bb7 = dup2(b47.w);
            FMA2(acc[0][0], a0, bb0); FMA2(acc[0][1], a0, bb1);
            FMA2(acc[0][2], a0, bb2); FMA2(acc[0][3], a0, bb3);
            FMA2(acc[0][4], a0, bb4); FMA2(acc[0][5], a0, bb5);
            FMA2(acc[0][6], a0, bb6); FMA2(acc[0][7], a0, bb7);
            FMA2(acc[1][0], a1, bb0); FMA2(acc[1][1], a1, bb1);
            FMA2(acc[1][2], a1, bb2); FMA2(acc[1][3], a1, bb3);
            FMA2(acc[1][4], a1, bb4); FMA2(acc[1][5], a1, bb5);
            FMA2(acc[1][6], a1, bb6); FMA2(acc[1][7], a1, bb7);
            FMA2(acc[2][0], a2, bb0); FMA2(acc[2][1], a2, bb1);
            FMA2(acc[2][2], a2, bb2); FMA2(acc[2][3], a2, bb3);
            FMA2(acc[2][4], a2, bb4); FMA2(acc[2][5], a2, bb5);
            FMA2(acc[2][6], a2, bb6); FMA2(acc[2][7], a2, bb7);
            FMA2(acc[3][0], a3, bb0); FMA2(acc[3][1], a3, bb1);
            FMA2(acc[3][2], a3, bb2); FMA2(acc[3][3], a3, bb3);
            FMA2(acc[3][4], a3, bb4); FMA2(acc[3][5], a3, bb5);
            FMA2(acc[3][6], a3, bb6); FMA2(acc[3][7], a3, bb7);
        }
        __syncthreads();
    }

    // ---- fused second layer: silu + dot(w2), reduce over ng lanes ----
    const int n0 = ng * 8;
    float b1v[8], w2a[8], w2b[8];
#pragma unroll
    for (int j = 0; j < 8; j++) {
        b1v[j] = B1[n0 + j];
        if (head) { w2a[j] = vW2[2 * (n0 + j)]; w2b[j] = vW2[2 * (n0 + j) + 1]; }
        else      { w2a[j] = qW2[n0 + j];       w2b[j] = 0.0f; }
    }

#pragma unroll
    for (int p = 0; p < 4; p++) {
        float s0a = 0.f, s1a = 0.f, s0b = 0.f, s1b = 0.f;
#pragma unroll
        for (int j = 0; j < 8; j++) {
            float ya, yb; unpack2(acc[p][j], ya, yb);
            float ha = siluf(ya + b1v[j]);
            float hb = siluf(yb + b1v[j]);
            s0a += ha * w2a[j]; s1a += ha * w2b[j];
            s0b += hb * w2a[j]; s1b += hb * w2b[j];
        }
#pragma unroll
        for (int m = 8; m >= 1; m >>= 1) {
            s0a += __shfl_xor_sync(0xFFFFFFFFu, s0a, m);
            s1a += __shfl_xor_sync(0xFFFFFFFFu, s1a, m);
            s0b += __shfl_xor_sync(0xFFFFFFFFu, s0b, m);
            s1b += __shfl_xor_sync(0xFFFFFFFFu, s1b, m);
        }
        if (ng == 0) {
            int a0i = mbase + mg * 8 + 2 * p;
            if (head == 0) {
                g_q[a0i]     = s0a;
                g_q[a0i + 1] = s0b;
            } else {
                float c6a = softplusf(s0a + vb2[0]);
                float rva = softplusf(s1a + vb2[1]);
                g_sc6[a0i] = sqrtf(c6a);
                g_r3[a0i]  = rva * rva * rva;
                float c6b = softplusf(s0b + vb2[0]);
                float rvb = softplusf(s1b + vb2[1]);
                g_sc6[a0i + 1] = sqrtf(c6b);
                g_r3[a0i + 1]  = rvb * rvb * rvb;
            }
        }
    }
}

// ================= K2: pairwise + full reduction (staged, in-block mean) ====
__global__ __launch_bounds__(128) void pair_kernel(
    const float* __restrict__ pos,
    const float* __restrict__ sigma,
    float* __restrict__ out)
{
    __shared__ float sx[MAXC], sy[MAXC], sz[MAXC];
    __shared__ float sq[MAXC], sc[MAXC], sr[MAXC];
    __shared__ float wred[4];
    __shared__ float s_qm;

    const int bid = blockIdx.x;
    const int g  = bid / SPLIT;
    const int sp = bid % SPLIT;
    const int tid = threadIdx.x;
    const int lane = tid & 31;
    const int wrp  = tid >> 5;

    const int s = g_start[g];
    const int c = g_cnt[g];

    float qacc = 0.f;
    for (int t = tid; t < c; t += 128) {
        int j = s + t;
        sx[t] = pos[3 * j + 0];
        sy[t] = pos[3 * j + 1];
        sz[t] = pos[3 * j + 2];
        float qv = g_q[j];
        sq[t] = qv;  qacc += qv;
        sc[t] = g_sc6[j];
        sr[t] = g_r3[j];
    }
#pragma unroll
    for (int o = 16; o > 0; o >>= 1) qacc += __shfl_xor_sync(0xFFFFFFFFu, qacc, o);
    if (lane == 0) wred[wrp] = qacc;
    __syncthreads();
    if (tid == 0) s_qm = (wred[0] + wred[1] + wred[2] + wred[3]) / fmaxf((float)c, 1.0f);
    __syncthreads();
    const float qm = s_qm;
    for (int t = tid; t < c; t += 128) sq[t] -= qm;
    __syncthreads();

    const float invs = 1.0f / (1.41421356f * sigma[0]);
    const int wg = wrp + sp * 4;            // 0 .. SPLIT*4-1

    float eel = 0.f, evd = 0.f;
    for (int i = wg; i < c; i += SPLIT * 4) {
        float px = sx[i], py = sy[i], pz = sz[i];
        float qi = sq[i], c6i = sc[i], r3i = sr[i];
        for (int j = i + 1 + lane; j < c; j += 32) {
            float dx = px - sx[j];
            float dy = py - sy[j];
            float dz = pz - sz[j];
            float dsq = dx * dx + dy * dy + dz * dz;
            float dist = sqrtf(dsq + 1e-8f);
            eel += qi * sq[j] * __fdividef(erff(dist * invs), dist + 1e-8f);
            float damp = dsq * dsq * dsq + r3i * sr[j];
            evd -= __fdividef(c6i * sc[j], damp + 1e-8f);
        }
    }

    float tot = KE_CONST * eel + evd;   // unordered pairs: 2 * 0.5 = 1
#pragma unroll
    for (int o = 16; o > 0; o >>= 1) tot += __shfl_down_sync(0xFFFFFFFFu, tot, o);
    if (lane == 0) wred[wrp] = tot;
    __syncthreads();
    if (tid == 0) {
        double bsum = (double)(wred[0] + wred[1] + wred[2] + wred[3]);
        atomicAdd(&g_esum, bsum);
        __threadfence();
        unsigned t = atomicAdd(&g_done, 1u);
        if (t == gridDim.x - 1) {
            g_done = 0u;
            double total = atomicAdd(&g_esum, 0.0);
            out[0] = (float)total;
        }
    }
}

// ---------------- launch ----------------
extern "C" void kernel_launch(void* const* d_in, const int* in_sizes, int n_in,
                              void* d_out, int out_size) {
    const float* h0    = (const float*)d_in[0];
    const float* pos   = (const float*)d_in[2];
    const float* qW1   = (const float*)d_in[3];
    const float* qb1   = (const float*)d_in[4];
    const float* qW2   = (const float*)d_in[5];
    const float* sigma = (const float*)d_in[6];
    const float* vW1   = (const float*)d_in[7];
    const float* vb1   = (const float*)d_in[8];
    const float* vW2   = (const float*)d_in[9];
    const float* vb2   = (const float*)d_in[10];
    const int*   batch = (const int*)d_in[11];

    mlp_gemm_kernel<<<2 * MTILES + 1, 64>>>(h0, qW1, qb1, qW2,
                                            vW1, vb1, vW2, vb2, batch);
    pair_kernel<<<G * SPLIT, 128>>>(pos, sigma, (float*)d_out);
}